// round 10
// baseline (speedup 1.0000x reference)
#include <cuda_runtime.h>
#include <cstdint>

#define SEQ    512
#define BATCH  256
#define NIN    32
#define HID    128
#define NOUT   16
#define FEAT   9              // silu + 8 spline basis
#define K1X    (NIN * FEAT)   // 288
#define K1H    (HID * FEAT)   // 1152
#define KSPLIT 16
#define NBLK   128
#define XC_ROWS 32
#define AS_STRIDE 68          // 64 rows + pad
#define AS_ELEMS  (72 * AS_STRIDE)            // 4896 floats
#define REC_SMEM  (AS_ELEMS * 4 + 72 * 64 * 8) // 19584 + 36864 = 56448 bytes

typedef unsigned long long u64;

// ---------------- scratch (device globals; no allocation allowed) ----------
__device__ float g_XC[SEQ * BATCH * HID];          // [t][b][o] x-part contribution
__device__ float g_P[2][KSPLIT * BATCH * HID];     // [parity][ks][b][o] partials
__device__ float g_W1x[K1X * HID];                 // fused layer1 x-part weights
__device__ float g_W1h[K1H * HID];                 // fused layer1 h-part weights
__device__ float g_W2[K1H * NOUT];                 // fused layer2 weights
__device__ unsigned int g_bar_count;               // monotonic arrivals
__device__ volatile unsigned int g_bar_gen;        // completed step count

// ---------------- packed f32x2 helpers -------------------------------------
__device__ __forceinline__ u64 pack2(float x) {
    u64 r; asm("mov.b64 %0, {%1, %1};" : "=l"(r) : "f"(x)); return r;
}
__device__ __forceinline__ void fma2(u64& d, u64 a, u64 b) {
    asm("fma.rn.f32x2 %0, %1, %2, %0;" : "+l"(d) : "l"(a), "l"(b));
}
__device__ __forceinline__ void unpack2(u64 v, float& lo, float& hi) {
    asm("mov.b64 {%0, %1}, %2;" : "=f"(lo), "=f"(hi) : "l"(v));
}

// ---------------- closed-form uniform cubic B-spline ------------------------
// Knots t_j = -8.8 + 1.6*j, j=0..11. For x in [t_j, t_{j+1}) the only nonzero
// degree-3 basis functions are indices j-3..j with the standard cubic weights.
// Returns j (0..10) or -1 when x is outside the spline support (all-zero basis).
__device__ __forceinline__ int kan_spline(float x, float* w) {
    float p = (x + 8.8f) * 0.625f;          // 0.625 = 1/1.6 (exact)
    if (!(p >= 0.0f && p < 11.0f)) return -1;
    int j = (int)p;
    float u = p - (float)j;
    float v = 1.0f - u;
    float u2 = u * u, u3 = u2 * u;
    const float s6 = 1.0f / 6.0f;
    w[0] = v * v * v * s6;                              // B_{j-3}
    w[1] = (3.0f * u3 - 6.0f * u2 + 4.0f) * s6;         // B_{j-2}
    w[2] = (-3.0f * u3 + 3.0f * u2 + 3.0f * u + 1.0f) * s6; // B_{j-1}
    w[3] = u3 * s6;                                     // B_j
    return j;
}
__device__ __forceinline__ float silu_f(float x) {
    return x / (1.0f + __expf(-x));
}

// ---------------- weight fusion + barrier reset ----------------------------
__global__ void prep_kernel(const float* __restrict__ coef1, const float* __restrict__ sb1,
                            const float* __restrict__ sp1,   const float* __restrict__ coef2,
                            const float* __restrict__ sb2,   const float* __restrict__ sp2) {
    int idx = blockIdx.x * blockDim.x + threadIdx.x;
    if (idx == 0) { g_bar_count = 0u; g_bar_gen = 0u; }   // graph-replay determinism
    if (idx < (K1X + K1H) * HID) {
        int j = idx >> 7;        // 0..1439
        int o = idx & 127;
        int i = j / FEAT;        // 0..159
        int m = j % FEAT;
        float w = (m == 0) ? sb1[i * HID + o]
                           : coef1[(i * HID + o) * 8 + (m - 1)] * sp1[i * HID + o];
        if (i < NIN) g_W1x[j * HID + o] = w;
        else         g_W1h[(j - K1X) * HID + o] = w;
    }
    if (idx < K1H * NOUT) {
        int j = idx >> 4;
        int o = idx & 15;
        int i = j / FEAT;
        int m = j % FEAT;
        float w = (m == 0) ? sb2[i * NOUT + o]
                           : coef2[(i * NOUT + o) * 8 + (m - 1)] * sp2[i * NOUT + o];
        g_W2[j * NOUT + o] = w;
    }
}

// ---------------- XC precompute: x-part of layer1 for all timesteps --------
__global__ __launch_bounds__(256) void xc_kernel(const float* __restrict__ x) {
    __shared__ float fs[XC_ROWS * 289];   // row-major, 289 = 288 + pad
    int row0 = blockIdx.x * XC_ROWS;
    int tid = threadIdx.x;
    // cooperative zero (32*289 = 9248 floats = 2312 float4)
    for (int idx = tid; idx < 2312; idx += 256)
        reinterpret_cast<float4*>(fs)[idx] = make_float4(0.f, 0.f, 0.f, 0.f);
    __syncthreads();
#pragma unroll
    for (int q = 0; q < 4; q++) {
        int e = tid + q * 256;            // 1024 (row,input) evals
        int r = e >> 5, i = e & 31;
        int rid = row0 + r;
        int t = rid >> 8, b = rid & 255;
        float xv = x[(b * SEQ + t) * NIN + i];
        float* frow = &fs[r * 289 + i * FEAT];
        frow[0] = silu_f(xv);
        float w[4]; int j = kan_spline(xv, w);
        if (j >= 0) {
#pragma unroll
            for (int c = 0; c < 4; c++) {
                int m = j - 3 + c;
                if (m >= 0 && m < 8) frow[1 + m] = w[c];
            }
        }
    }
    __syncthreads();
    int tx = tid & 31, ty = tid >> 5;     // 32 col-groups x 8 row-groups
    u64 acc[8];
#pragma unroll
    for (int u = 0; u < 8; u++) acc[u] = 0ull;
#pragma unroll 4
    for (int k = 0; k < K1X; k++) {
        u64 a0 = pack2(fs[(ty * 4 + 0) * 289 + k]);
        u64 a1 = pack2(fs[(ty * 4 + 1) * 289 + k]);
        u64 a2 = pack2(fs[(ty * 4 + 2) * 289 + k]);
        u64 a3 = pack2(fs[(ty * 4 + 3) * 289 + k]);
        ulonglong2 bb = *reinterpret_cast<const ulonglong2*>(&g_W1x[k * HID + tx * 4]);
        fma2(acc[0], a0, bb.x); fma2(acc[1], a0, bb.y);
        fma2(acc[2], a1, bb.x); fma2(acc[3], a1, bb.y);
        fma2(acc[4], a2, bb.x); fma2(acc[5], a2, bb.y);
        fma2(acc[6], a3, bb.x); fma2(acc[7], a3, bb.y);
    }
#pragma unroll
    for (int q = 0; q < 4; q++) {
        int rid = row0 + ty * 4 + q;
        float4 v;
        unpack2(acc[2 * q + 0], v.x, v.y);
        unpack2(acc[2 * q + 1], v.z, v.w);
        *reinterpret_cast<float4*>(&g_XC[rid * HID + tx * 4]) = v;
    }
}

// ---------------- grid barrier (128 co-resident blocks) --------------------
__device__ __forceinline__ void grid_barrier(unsigned int target) {
    __threadfence();            // release this thread's P stores to L2
    __syncthreads();
    if (threadIdx.x == 0) {
        unsigned int arrived = atomicAdd(&g_bar_count, 1u) + 1u;
        if (arrived == target * NBLK) {
            g_bar_gen = target;                 // volatile store, L2
        } else {
            while (g_bar_gen < target) { __nanosleep(32); }
        }
    }
    __syncthreads();
}

// ---------------- persistent recurrent kernel ------------------------------
// 128 blocks = 4 M-tiles(64 rows) x 2 N-tiles(64 cols) x 16 K-tiles(8 inputs).
__global__ __launch_bounds__(256, 1) void rec_kernel() {
    extern __shared__ float smem_dyn[];
    float* As = smem_dyn;                                  // [72][AS_STRIDE] k-major
    u64*   Bsd = reinterpret_cast<u64*>(smem_dyn + AS_ELEMS); // [72][64] dup pairs
    int bid = blockIdx.x;
    int ks = bid & 15;
    int ni = (bid >> 4) & 1;
    int mi = bid >> 5;
    int b0 = mi * 64, o0 = ni * 64, i0 = ks * 8, j0 = ks * 72;
    int tid = threadIdx.x;
    for (int idx = tid; idx < 72 * 64; idx += 256)
        Bsd[idx] = pack2(g_W1h[(j0 + (idx >> 6)) * HID + o0 + (idx & 63)]);
    __syncthreads();
    int tx = tid & 15, ty = tid >> 4;
    int rA = tid >> 2, gA = tid & 3;      // phase-A mapping: row rA, input pair gA*2

    for (int t = 0; t < SEQ; t++) {
        // ---- phase A: zero A-tile, then scatter features of h_{t-1}
#pragma unroll
        for (int z = 0; z < 5; z++) {
            int idx = tid + z * 256;
            if (idx < AS_ELEMS / 4)
                reinterpret_cast<float4*>(As)[idx] = make_float4(0.f, 0.f, 0.f, 0.f);
        }
        __syncthreads();
        {
            int b = b0 + rA, il = gA * 2;
            float hx = 0.0f, hy = 0.0f;
            if (t > 0) {
                const float* __restrict__ xcp = g_XC + (size_t)(t - 1) * BATCH * HID;
                const float2* __restrict__ Pold =
                    reinterpret_cast<const float2*>(g_P[(t + 1) & 1]) + (b * HID + i0 + il) / 2;
                float2 h2 = *reinterpret_cast<const float2*>(&xcp[b * HID + i0 + il]);
                hx = h2.x; hy = h2.y;
#pragma unroll
                for (int s = 0; s < KSPLIT; s++) {
                    float2 p = __ldcg(Pold + s * (BATCH * HID / 2));
                    hx += p.x; hy += p.y;
                }
            }
#pragma unroll
            for (int half = 0; half < 2; half++) {
                float hv = half ? hy : hx;
                int kb = (il + half) * FEAT;
                As[kb * AS_STRIDE + rA] = silu_f(hv);
                float w[4]; int j = kan_spline(hv, w);
                if (j >= 0) {
#pragma unroll
                    for (int c = 0; c < 4; c++) {
                        int m = j - 3 + c;
                        if (m >= 0 && m < 8) As[(kb + 1 + m) * AS_STRIDE + rA] = w[c];
                    }
                }
            }
        }
        __syncthreads();

        // ---- phase B: 64x64x72 GEMM; rows paired in f32x2, B pre-duplicated
        u64 acc[8];
#pragma unroll
        for (int u = 0; u < 8; u++) acc[u] = 0ull;
#pragma unroll 4
        for (int k = 0; k < 72; k++) {
            ulonglong2 a = *reinterpret_cast<const ulonglong2*>(&As[k * AS_STRIDE + ty * 4]);
            ulonglong2 bA = *reinterpret_cast<const ulonglong2*>(&Bsd[k * 64 + tx * 4]);
            ulonglong2 bB = *reinterpret_cast<const ulonglong2*>(&Bsd[k * 64 + tx * 4 + 2]);
            fma2(acc[0], a.x, bA.x); fma2(acc[1], a.x, bA.y);
            fma2(acc[2], a.x, bB.x); fma2(acc[3], a.x, bB.y);
            fma2(acc[4], a.y, bA.x); fma2(acc[5], a.y, bA.y);
            fma2(acc[6], a.y, bB.x); fma2(acc[7], a.y, bB.y);
        }
        float* __restrict__ Pnew = g_P[t & 1];
        {
            float4 v0, v1, v2, v3;
            unpack2(acc[0], v0.x, v1.x); unpack2(acc[1], v0.y, v1.y);
            unpack2(acc[2], v0.z, v1.z); unpack2(acc[3], v0.w, v1.w);
            unpack2(acc[4], v2.x, v3.x); unpack2(acc[5], v2.y, v3.y);
            unpack2(acc[6], v2.z, v3.z); unpack2(acc[7], v2.w, v3.w);
            int rbase = (ks * BATCH + b0 + ty * 4) * HID + o0 + tx * 4;
            *reinterpret_cast<float4*>(&Pnew[rbase + 0 * HID]) = v0;
            *reinterpret_cast<float4*>(&Pnew[rbase + 1 * HID]) = v1;
            *reinterpret_cast<float4*>(&Pnew[rbase + 2 * HID]) = v2;
            *reinterpret_cast<float4*>(&Pnew[rbase + 3 * HID]) = v3;
        }
        if (t < SEQ - 1) grid_barrier((unsigned int)(t + 1));
    }
}

// ---------------- layer 2 on final hidden state ----------------------------
__global__ __launch_bounds__(128) void out_kernel(float* __restrict__ out) {
    __shared__ float fs[K1H];
    int b = blockIdx.x;
    int tid = threadIdx.x;                       // tid == input index i
    for (int idx = tid; idx < K1H / 4; idx += 128)
        reinterpret_cast<float4*>(fs)[idx] = make_float4(0.f, 0.f, 0.f, 0.f);
    __syncthreads();
    float hv = g_XC[((SEQ - 1) * BATCH + b) * HID + tid];
    const float* __restrict__ P = g_P[(SEQ - 1) & 1];
#pragma unroll
    for (int s = 0; s < KSPLIT; s++) hv += P[(s * BATCH + b) * HID + tid];
    float* frow = &fs[tid * FEAT];
    frow[0] = silu_f(hv);
    {
        float w[4]; int j = kan_spline(hv, w);
        if (j >= 0) {
#pragma unroll
            for (int c = 0; c < 4; c++) {
                int m = j - 3 + c;
                if (m >= 0 && m < 8) frow[1 + m] = w[c];
            }
        }
    }
    __syncthreads();
    int o = tid >> 3, part = tid & 7;            // 16 outputs x 8-way split
    float sum = 0.0f;
    for (int j = part; j < K1H; j += 8) sum += fs[j] * g_W2[j * NOUT + o];
    sum += __shfl_down_sync(0xffffffffu, sum, 4, 8);
    sum += __shfl_down_sync(0xffffffffu, sum, 2, 8);
    sum += __shfl_down_sync(0xffffffffu, sum, 1, 8);
    if (part == 0) out[b * NOUT + o] = sum;
}

// ---------------- launch ----------------------------------------------------
extern "C" void kernel_launch(void* const* d_in, const int* in_sizes, int n_in,
                              void* d_out, int out_size) {
    const float* x     = (const float*)d_in[0];
    const float* coef1 = (const float*)d_in[1];
    const float* sb1   = (const float*)d_in[2];
    const float* sp1   = (const float*)d_in[3];
    const float* coef2 = (const float*)d_in[4];
    const float* sb2   = (const float*)d_in[5];
    const float* sp2   = (const float*)d_in[6];
    float* out = (float*)d_out;

    static bool attr_done = false;
    if (!attr_done) {
        cudaFuncSetAttribute(rec_kernel, cudaFuncAttributeMaxDynamicSharedMemorySize, REC_SMEM);
        attr_done = true;
    }

    prep_kernel<<<((K1X + K1H) * HID + 255) / 256, 256>>>(coef1, sb1, sp1, coef2, sb2, sp2);
    xc_kernel<<<(SEQ * BATCH) / XC_ROWS, 256>>>(x);
    rec_kernel<<<NBLK, 256, REC_SMEM>>>();
    out_kernel<<<BATCH, 128>>>(out);
}

// round 12
// speedup vs baseline: 1.6824x; 1.6824x over previous
#include <cuda_runtime.h>
#include <cstdint>

#define SEQ    512
#define BATCH  256
#define NIN    32
#define HID    128
#define NOUT   16
#define FEAT   9              // silu + 8 spline basis
#define K1X    (NIN * FEAT)   // 288
#define K1H    (HID * FEAT)   // 1152
#define KSPLIT 16
#define NBLK   128
#define XC_ROWS 32
#define AS_STRIDE 68          // 64 rows + pad (k-major A tile)

typedef unsigned long long u64;

// ---------------- scratch (device globals; no allocation allowed) ----------
__device__ float g_XC[SEQ * BATCH * HID];          // [t][b][o] x-part contribution
__device__ float g_P[2][KSPLIT * BATCH * HID];     // [parity][ks][b][o] partials
__device__ float g_W1x[K1X * HID];                 // fused layer1 x-part weights
__device__ float g_W1h[K1H * HID];                 // fused layer1 h-part weights
__device__ float g_W2[K1H * NOUT];                 // fused layer2 weights
__device__ unsigned int g_bar_count;               // monotonic arrivals
__device__ volatile unsigned int g_bar_gen;        // completed step count

// ---------------- packed f32x2 helpers -------------------------------------
__device__ __forceinline__ u64 pack2(float x) {
    u64 r; asm("mov.b64 %0, {%1, %1};" : "=l"(r) : "f"(x)); return r;
}
__device__ __forceinline__ void fma2(u64& d, u64 a, u64 b) {
    asm("fma.rn.f32x2 %0, %1, %2, %0;" : "+l"(d) : "l"(a), "l"(b));
}
__device__ __forceinline__ void unpack2(u64 v, float& lo, float& hi) {
    asm("mov.b64 {%0, %1}, %2;" : "=f"(lo), "=f"(hi) : "l"(v));
}

// ---------------- closed-form uniform cubic B-spline -> dense 9 features ---
// Knots t_j = -8.8 + 1.6*j (j=0..11). For x in [t_j, t_{j+1}) only bases
// j-3..j are nonzero with the standard cubic weights (basis j-3 gets (1-u)^3/6,
// basis j gets u^3/6); indices outside 0..7 drop. Identical mapping to the
// R9 scatter version that passed at rel_err 3.8e-7.
__device__ __forceinline__ void kan_feats9(float x, float* f) {
    f[0] = x / (1.0f + __expf(-x));                 // silu
    float p = (x + 8.8f) * 0.625f;                  // 0.625 = 1/1.6 exact
    int j = (p >= 0.0f && p < 11.0f) ? (int)p : -1; // -1 -> all basis zero
    float u = p - (float)j;                         // unused when j < 0
    float v = 1.0f - u;
    float u2 = u * u, u3 = u2 * u;
    const float s6 = 1.0f / 6.0f;
    float w0 = v * v * v * s6;                                  // basis j-3
    float w1 = (3.0f * u3 - 6.0f * u2 + 4.0f) * s6;             // basis j-2
    float w2 = (-3.0f * u3 + 3.0f * u2 + 3.0f * u + 1.0f) * s6; // basis j-1
    float w3 = u3 * s6;                                         // basis j
#pragma unroll
    for (int m = 0; m < 8; m++) {
        float val = 0.0f;
        val = (j == m + 3) ? w0 : val;
        val = (j == m + 2) ? w1 : val;
        val = (j == m + 1) ? w2 : val;
        val = (j == m    ) ? w3 : val;
        f[1 + m] = val;
    }
}

// ---------------- weight fusion + barrier reset ----------------------------
__global__ void prep_kernel(const float* __restrict__ coef1, const float* __restrict__ sb1,
                            const float* __restrict__ sp1,   const float* __restrict__ coef2,
                            const float* __restrict__ sb2,   const float* __restrict__ sp2) {
    int idx = blockIdx.x * blockDim.x + threadIdx.x;
    if (idx == 0) { g_bar_count = 0u; g_bar_gen = 0u; }   // graph-replay determinism
    if (idx < (K1X + K1H) * HID) {
        int j = idx >> 7;        // 0..1439
        int o = idx & 127;
        int i = j / FEAT;        // 0..159
        int m = j % FEAT;
        float w = (m == 0) ? sb1[i * HID + o]
                           : coef1[(i * HID + o) * 8 + (m - 1)] * sp1[i * HID + o];
        if (i < NIN) g_W1x[j * HID + o] = w;
        else         g_W1h[(j - K1X) * HID + o] = w;
    }
    if (idx < K1H * NOUT) {
        int j = idx >> 4;
        int o = idx & 15;
        int i = j / FEAT;
        int m = j % FEAT;
        float w = (m == 0) ? sb2[i * NOUT + o]
                           : coef2[(i * NOUT + o) * 8 + (m - 1)] * sp2[i * NOUT + o];
        g_W2[j * NOUT + o] = w;
    }
}

// ---------------- XC precompute: x-part of layer1 for all timesteps --------
__global__ __launch_bounds__(256) void xc_kernel(const float* __restrict__ x) {
    __shared__ float fs[XC_ROWS * 289];   // row-major, 289 = 288 + pad
    int row0 = blockIdx.x * XC_ROWS;
    int tid = threadIdx.x;
#pragma unroll
    for (int q = 0; q < 4; q++) {
        int e = tid + q * 256;            // 1024 (row,input) evals
        int r = e >> 5, i = e & 31;
        int rid = row0 + r;
        int t = rid >> 8, b = rid & 255;
        float xv = x[(b * SEQ + t) * NIN + i];
        float f[FEAT];
        kan_feats9(xv, f);
        float* frow = &fs[r * 289 + i * FEAT];
#pragma unroll
        for (int m = 0; m < FEAT; m++) frow[m] = f[m];
    }
    __syncthreads();
    int tx = tid & 31, ty = tid >> 5;     // 32 col-groups x 8 row-groups
    u64 acc[8];
#pragma unroll
    for (int u = 0; u < 8; u++) acc[u] = 0ull;
#pragma unroll 4
    for (int k = 0; k < K1X; k++) {
        u64 a0 = pack2(fs[(ty * 4 + 0) * 289 + k]);
        u64 a1 = pack2(fs[(ty * 4 + 1) * 289 + k]);
        u64 a2 = pack2(fs[(ty * 4 + 2) * 289 + k]);
        u64 a3 = pack2(fs[(ty * 4 + 3) * 289 + k]);
        ulonglong2 bb = *reinterpret_cast<const ulonglong2*>(&g_W1x[k * HID + tx * 4]);
        fma2(acc[0], a0, bb.x); fma2(acc[1], a0, bb.y);
        fma2(acc[2], a1, bb.x); fma2(acc[3], a1, bb.y);
        fma2(acc[4], a2, bb.x); fma2(acc[5], a2, bb.y);
        fma2(acc[6], a3, bb.x); fma2(acc[7], a3, bb.y);
    }
#pragma unroll
    for (int q = 0; q < 4; q++) {
        int rid = row0 + ty * 4 + q;
        float4 v;
        unpack2(acc[2 * q + 0], v.x, v.y);
        unpack2(acc[2 * q + 1], v.z, v.w);
        *reinterpret_cast<float4*>(&g_XC[rid * HID + tx * 4]) = v;
    }
}

// ---------------- grid barrier (PROVEN R8 version — do not modify) ---------
// Release: per-thread membar.gl orders P stores to L2 before the L2-serialized
// atomicAdd. The last arriver publishes gen AFTER its RMW returned the full
// count (control dependency), giving waiters causality through the atomic
// chain. Readers use __ldcg (L2 coherence point), so no acquire fence needed.
__device__ __forceinline__ void grid_barrier(unsigned int target) {
    __threadfence();            // release this thread's P stores
    __syncthreads();
    if (threadIdx.x == 0) {
        unsigned int arrived = atomicAdd(&g_bar_count, 1u) + 1u;
        if (arrived == target * NBLK) {
            g_bar_gen = target;                 // volatile store, L2
        } else {
            while (g_bar_gen < target) { __nanosleep(32); }
        }
    }
    __syncthreads();
}

// ---------------- persistent recurrent kernel ------------------------------
// 128 blocks = 4 M-tiles(64 rows) x 2 N-tiles(64 cols) x 16 K-tiles(8 inputs).
__global__ __launch_bounds__(256, 1) void rec_kernel() {
    __shared__ float As[72 * AS_STRIDE];   // k-major: As[k*68 + r]
    __shared__ float Bs[72 * 64];          // W1h tile, resident across steps
    int bid = blockIdx.x;
    int ks = bid & 15;
    int ni = (bid >> 4) & 1;
    int mi = bid >> 5;
    int b0 = mi * 64, o0 = ni * 64, i0 = ks * 8, j0 = ks * 72;
    int tid = threadIdx.x;
    for (int idx = tid; idx < 72 * 64; idx += 256)
        Bs[idx] = g_W1h[(j0 + (idx >> 6)) * HID + o0 + (idx & 63)];
    int tx = tid & 15, ty = tid >> 4;
    int rA = tid >> 2, il2 = (tid & 3) * 2;   // phase-A: row rA, inputs il2, il2+1

    for (int t = 0; t < SEQ; t++) {
        // ---- phase A: features of h_{t-1}; dense select-based writes
        {
            float hx = 0.0f, hy = 0.0f;
            if (t > 0) {
                const float* __restrict__ xcp = g_XC + (size_t)(t - 1) * BATCH * HID;
                int b = b0 + rA;
                float2 h2 = *reinterpret_cast<const float2*>(&xcp[b * HID + i0 + il2]);
                hx = h2.x; hy = h2.y;
                const float2* __restrict__ Pold =
                    reinterpret_cast<const float2*>(g_P[(t + 1) & 1]) + (b * HID + i0 + il2) / 2;
#pragma unroll
                for (int s = 0; s < KSPLIT; s++) {
                    float2 p = __ldcg(Pold + s * (BATCH * HID / 2));
                    hx += p.x; hy += p.y;
                }
            }
#pragma unroll
            for (int half = 0; half < 2; half++) {
                float hv = half ? hy : hx;
                float f[FEAT];
                kan_feats9(hv, f);
                float* col = &As[(il2 + half) * FEAT * AS_STRIDE + rA];
#pragma unroll
                for (int m = 0; m < FEAT; m++) col[m * AS_STRIDE] = f[m];
            }
        }
        __syncthreads();

        // ---- phase B: 64x64x72 GEMM, 4x4 tile, cols paired in f32x2
        u64 acc[8];
#pragma unroll
        for (int u = 0; u < 8; u++) acc[u] = 0ull;
#pragma unroll 4
        for (int k = 0; k < 72; k++) {
            float4 av = *reinterpret_cast<const float4*>(&As[k * AS_STRIDE + ty * 4]);
            ulonglong2 bb = *reinterpret_cast<const ulonglong2*>(&Bs[k * 64 + tx * 4]);
            u64 a0 = pack2(av.x), a1 = pack2(av.y), a2 = pack2(av.z), a3 = pack2(av.w);
            fma2(acc[0], a0, bb.x); fma2(acc[1], a0, bb.y);
            fma2(acc[2], a1, bb.x); fma2(acc[3], a1, bb.y);
            fma2(acc[4], a2, bb.x); fma2(acc[5], a2, bb.y);
            fma2(acc[6], a3, bb.x); fma2(acc[7], a3, bb.y);
        }
        float* __restrict__ Pnew = g_P[t & 1];
#pragma unroll
        for (int q = 0; q < 4; q++) {
            int b = b0 + ty * 4 + q;
            float4 v;
            unpack2(acc[2 * q + 0], v.x, v.y);
            unpack2(acc[2 * q + 1], v.z, v.w);
            *reinterpret_cast<float4*>(&Pnew[(ks * BATCH + b) * HID + o0 + tx * 4]) = v;
        }
        __syncthreads();                  // all stores issued before arrival
        if (t < SEQ - 1) grid_barrier((unsigned int)(t + 1));
    }
}

// ---------------- layer 2 on final hidden state ----------------------------
__global__ __launch_bounds__(128) void out_kernel(float* __restrict__ out) {
    __shared__ float fs[K1H];
    int b = blockIdx.x;
    int tid = threadIdx.x;                       // tid == input index i
    float hv = g_XC[((SEQ - 1) * BATCH + b) * HID + tid];
    const float* __restrict__ P = g_P[(SEQ - 1) & 1];
#pragma unroll
    for (int s = 0; s < KSPLIT; s++) hv += P[(s * BATCH + b) * HID + tid];
    float f[FEAT];
    kan_feats9(hv, f);
#pragma unroll
    for (int m = 0; m < FEAT; m++) fs[tid * FEAT + m] = f[m];
    __syncthreads();
    int o = tid >> 3, part = tid & 7;            // 16 outputs x 8-way split
    float sum = 0.0f;
    for (int j = part; j < K1H; j += 8) sum += fs[j] * g_W2[j * NOUT + o];
    sum += __shfl_down_sync(0xffffffffu, sum, 4, 8);
    sum += __shfl_down_sync(0xffffffffu, sum, 2, 8);
    sum += __shfl_down_sync(0xffffffffu, sum, 1, 8);
    if (part == 0) out[b * NOUT + o] = sum;
}

// ---------------- launch ----------------------------------------------------
extern "C" void kernel_launch(void* const* d_in, const int* in_sizes, int n_in,
                              void* d_out, int out_size) {
    const float* x     = (const float*)d_in[0];
    const float* coef1 = (const float*)d_in[1];
    const float* sb1   = (const float*)d_in[2];
    const float* sp1   = (const float*)d_in[3];
    const float* coef2 = (const float*)d_in[4];
    const float* sb2   = (const float*)d_in[5];
    const float* sp2   = (const float*)d_in[6];
    float* out = (float*)d_out;

    prep_kernel<<<((K1X + K1H) * HID + 255) / 256, 256>>>(coef1, sb1, sp1, coef2, sb2, sp2);
    xc_kernel<<<(SEQ * BATCH) / XC_ROWS, 256>>>(x);
    rec_kernel<<<NBLK, 256>>>();
    out_kernel<<<BATCH, 128>>>(out);
}